// round 15
// baseline (speedup 1.0000x reference)
#include <cuda_runtime.h>
#include <math.h>

#define B 2
#define NF 20000
#define NS 30000
#define C 128
#define NKEY 500
#define NROWS (B*NF)
#define NK_TOT (B*NKEY)   // 1000

// output layout (flattened, float32, in reference return order)
#define OUT_OFF  0        // (1000,128)
#define KVI_OFF  128000   // (1000,3)
#define HEAT_OFF 131000   // (40000,)
#define S10_OFF  171000   // (40000,10)
#define KC_OFF   571000   // (1000,)

// spatial binning params (cell > radius with wide margin -> 3x3 ring suffices)
#define DIM0 36
#define CELL0 3.0f
#define DIM1 22
#define CELL1 5.0f
#define NCELLMAX (DIM0*DIM0)   // 1296
#define CAP 192                // fixed per-cell capacity (avg 23 / 62; huge margin)

#define SENT 0xFFFFFFFFFFFFFFFFull
#define INVIDX 0xFFFFFFFFu

// ---------------- scratch (device globals; no allocs allowed) ----------------
__device__ float g_sig[NROWS];
__device__ int   g_cls[NROWS];
__device__ int   g_topk[NK_TOT];
__device__ float2 g_keyworld[NK_TOT];
__device__ int    g_cellcnt[2][B][NCELLMAX];
__device__ float4 g_cellpts[2][B][NCELLMAX*CAP];   // {wx, wy, idx-bits, 0}

__device__ __forceinline__ float worldc(int c, float stride) {
    float t = __fadd_rn((float)c, 0.5f);
    t = __fmul_rn(t, stride);
    t = __fmul_rn(t, 0.075f);
    return __fadd_rn(t, -54.0f);
}

// ---------------- K0: zero cell counts (before this call's bin build) --------
__global__ void cellreset_kernel() {
    int i = blockIdx.x * 1024 + threadIdx.x;
    if (i < 2 * B * NCELLMAX) ((int*)g_cellcnt)[i] = 0;
}

// ---------------- K1: heat MLP (40000 x 128 -> 128 relu -> 10) ----------------
#define SXS 132
#define HEAT_SMEM ((64*SXS + 128*12 + 64*10) * 4)
#define BIN_PER_BLOCK 192   // 625 blocks * 192 = 120000 = 2*B*NS exactly

__global__ void __launch_bounds__(256) heat_kernel(
    const float* __restrict__ X, const float* __restrict__ W1,
    const float* __restrict__ G1, const float* __restrict__ B1,
    const float* __restrict__ W2, const float* __restrict__ B2v,
    const int* __restrict__ ca, const int* __restrict__ cb,
    float* __restrict__ outF)
{
    extern __shared__ float sm[];
    float* sX  = sm;                     // 64 * SXS
    float* sW2 = sm + 64 * SXS;          // 128 * 12
    float* sS  = sW2 + 128 * 12;         // 64 * 10
    const int tid = threadIdx.x;
    const int rowbase = blockIdx.x * 64;

    // ---- bin-build prologue ----
    if (tid < BIN_PER_BLOCK) {
        int id = blockIdx.x * BIN_PER_BLOCK + tid;
        int src = id / (B * NS);
        int rem = id - src * (B * NS);
        int b = rem / NS, i = rem - b * NS;
        int2 cc = ((const int2*)(src == 0 ? ca : cb))[b * NS + i];
        float stride = (src == 0) ? 4.0f : 8.0f;
        float wx = worldc(cc.x, stride), wy = worldc(cc.y, stride);
        float cell = (src == 0) ? CELL0 : CELL1;
        int dim = (src == 0) ? DIM0 : DIM1;
        int cx = min(dim - 1, max(0, (int)floorf((wx + 54.0f) / cell)));
        int cy = min(dim - 1, max(0, (int)floorf((wy + 54.0f) / cell)));
        int cid = cy * dim + cx;
        int pos = atomicAdd(&g_cellcnt[src][b][cid], 1);
        if (pos < CAP)
            g_cellpts[src][b][cid * CAP + pos] =
                make_float4(wx, wy, __uint_as_float((unsigned)i), 0.f);
    }

    {
        const float4* s = (const float4*)(X + (size_t)rowbase * C);
        #pragma unroll
        for (int t = 0; t < 8; ++t) {
            int idx = tid + t * 256;
            int row = idx >> 5, c4 = idx & 31;
            *(float4*)(sX + row * SXS + c4 * 4) = s[idx];
        }
    }
    for (int t = tid; t < 128 * 12; t += 256) {
        int i = t / 12, c = t - i * 12;
        sW2[t] = (c < 10) ? W2[i * 10 + c] : 0.f;
    }
    __syncthreads();

    const int ty = tid >> 4, tx = tid & 15;
    const int r0 = ty * 4, c0 = tx * 8;
    float acc[4][8];
    #pragma unroll
    for (int i = 0; i < 4; ++i)
        #pragma unroll
        for (int j = 0; j < 8; ++j) acc[i][j] = 0.f;

    #pragma unroll 2
    for (int k = 0; k < 128; k += 4) {
        float4 w[8];
        #pragma unroll
        for (int kk = 0; kk < 4; ++kk) {
            w[2*kk]   = __ldg((const float4*)(W1 + (k + kk) * 128 + c0));
            w[2*kk+1] = __ldg((const float4*)(W1 + (k + kk) * 128 + c0 + 4));
        }
        float4 xr[4];
        #pragma unroll
        for (int i = 0; i < 4; ++i)
            xr[i] = *(const float4*)&sX[(r0 + i) * SXS + k];
        #pragma unroll
        for (int kk = 0; kk < 4; ++kk) {
            #pragma unroll
            for (int i = 0; i < 4; ++i) {
                float x = (kk == 0) ? xr[i].x : (kk == 1) ? xr[i].y
                        : (kk == 2) ? xr[i].z : xr[i].w;
                acc[i][0] += x * w[2*kk].x;   acc[i][1] += x * w[2*kk].y;
                acc[i][2] += x * w[2*kk].z;   acc[i][3] += x * w[2*kk].w;
                acc[i][4] += x * w[2*kk+1].x; acc[i][5] += x * w[2*kk+1].y;
                acc[i][6] += x * w[2*kk+1].z; acc[i][7] += x * w[2*kk+1].w;
            }
        }
    }
    float4 ga = *(const float4*)&G1[c0], gb = *(const float4*)&G1[c0 + 4];
    float4 ba = *(const float4*)&B1[c0], bb = *(const float4*)&B1[c0 + 4];
    float gv[8] = {ga.x, ga.y, ga.z, ga.w, gb.x, gb.y, gb.z, gb.w};
    float bv[8] = {ba.x, ba.y, ba.z, ba.w, bb.x, bb.y, bb.z, bb.w};
    __syncthreads();
    #pragma unroll
    for (int i = 0; i < 4; ++i)
        #pragma unroll
        for (int j = 0; j < 8; ++j) {
            float h = acc[i][j] * gv[j] + bv[j];
            sX[(r0 + i) * SXS + c0 + j] = h > 0.f ? h : 0.f;
        }
    __syncthreads();

    if (tid < 128) {
        const int r = tid >> 1, hhalf = tid & 1;
        const int cc0 = hhalf * 5;
        float a[5] = {0.f, 0.f, 0.f, 0.f, 0.f};
        for (int i = 0; i < 128; ++i) {
            float hv = sX[r * SXS + i];
            #pragma unroll
            for (int q = 0; q < 5; ++q) a[q] += hv * sW2[i * 12 + cc0 + q];
        }
        #pragma unroll
        for (int q = 0; q < 5; ++q) {
            int c = cc0 + q;
            float v = a[q] + B2v[c];
            outF[S10_OFF + (size_t)(rowbase + r) * 10 + c] = v;
            sS[r * 10 + c] = v;
        }
    }
    __syncthreads();
    if (tid < 64) {
        int r = tid, row = rowbase + r;
        float m = -INFINITY; int a = 0;
        #pragma unroll
        for (int c = 0; c < 10; ++c) {
            float v = sS[r * 10 + c];
            if (v > m) { m = v; a = c; }
        }
        outF[HEAT_OFF + row] = m;
        g_sig[row] = 1.f / (1.f + expf(-m));
        g_cls[row] = a;
    }
}

// ---------------- K2: per-batch top-500 (jax.lax.top_k semantics) ----------------
#define VPT 20
#define CANDMAX 2048
#define TOPK_SMEM (CANDMAX * 8)

__global__ void __launch_bounds__(1024) topk_kernel(
    const int* __restrict__ fusion_coords, float* __restrict__ outF)
{
    extern __shared__ unsigned char dsm[];
    unsigned long long* cand = (unsigned long long*)dsm;
    __shared__ int s_cnt[32];
    __shared__ int s_n;
    const int tid = threadIdx.x;
    const int lane = tid & 31;
    const int b = blockIdx.x;

    unsigned vals[VPT];
    #pragma unroll
    for (int t = 0; t < VPT; ++t) {
        int i = tid + t * 1024;
        vals[t] = (i < NF) ? __float_as_uint(g_sig[b * NF + i]) : 0u;
    }
    if (tid < 32) s_cnt[tid] = 0;
    if (tid == 0) s_n = 0;
    cand[tid] = 0ull;
    cand[tid + 1024] = 0ull;
    __syncthreads();

    unsigned lo = 0u, hi = 0x3F800000u;
    #pragma unroll 1
    for (int it = 0; it < 31; ++it) {
        unsigned mid = lo + ((hi - lo) >> 1);
        int c = 0;
        #pragma unroll
        for (int t = 0; t < VPT; ++t) c += (vals[t] >= mid) ? 1 : 0;
        #pragma unroll
        for (int o = 16; o; o >>= 1) c += __shfl_xor_sync(0xffffffffu, c, o);
        if (lane == 0 && c) atomicAdd(&s_cnt[it], c);
        __syncthreads();
        if (s_cnt[it] >= NKEY) lo = mid; else hi = mid;
    }
    const unsigned thr = lo;

    #pragma unroll
    for (int t = 0; t < VPT; ++t) {
        unsigned v = vals[t];
        if (v >= thr) {
            int i = tid + t * 1024;
            int p = atomicAdd(&s_n, 1);
            if (p < CANDMAX)
                cand[p] = ((unsigned long long)v << 32) |
                          (unsigned long long)(0xFFFFFFFFu - (unsigned)i);
        }
    }
    __syncthreads();
    int n = s_n; if (n > CANDMAX) n = CANDMAX;

    for (int s = tid; s < CANDMAX; s += 1024) {
        unsigned long long mine = cand[s];
        if (mine == 0ull || s >= n) continue;
        int rank = 0;
        for (int j = 0; j < n; ++j) rank += (cand[j] > mine) ? 1 : 0;
        if (rank < NKEY) {
            unsigned idx = 0xFFFFFFFFu - (unsigned)(mine & 0xFFFFFFFFull);
            g_topk[b * NKEY + rank] = (int)idx;
            int2 cc = ((const int2*)fusion_coords)[b * NF + (int)idx];
            int o = (b * NKEY + rank) * 3;
            outF[KVI_OFF + o + 0] = (float)b;
            outF[KVI_OFF + o + 1] = (float)cc.x;
            outF[KVI_OFF + o + 2] = (float)cc.y;
            g_keyworld[b * NKEY + rank] = make_float2(worldc(cc.x, 8.0f), worldc(cc.y, 8.0f));
            outF[KC_OFF + b * NKEY + rank] = (float)g_cls[b * NF + (int)idx];
        }
    }
}

// ---------------- K3: MEGAFUSE — 2 keys/block, grid 500, 256 threads ---------
// phase 1: warps 0-3 run the 4 (key,src) knn tasks; warps 4-7 gather kf
// phase 2: kw MLP + softmax + fused build
// phase 3a: fused @ fw1 + BN + ReLU -> sH
// phase 3b: sH @ fw2 + b2 -> out
#define KPB 2   // keys per block

__global__ void __launch_bounds__(256) megafuse_kernel(
    const float* __restrict__ fa, const float* __restrict__ fb,
    const float* __restrict__ knn_w, const float* __restrict__ knn_b,
    const float* __restrict__ fusion_feat,
    const float* __restrict__ kw1, const float* __restrict__ kg1,
    const float* __restrict__ kb1, const float* __restrict__ kw2,
    const float* __restrict__ kb2,
    const float* __restrict__ fw1, const float* __restrict__ fg1,
    const float* __restrict__ fb1, const float* __restrict__ fw2,
    const float* __restrict__ fb2, float* __restrict__ outF)
{
    __shared__ float smf[2][KPB][128];
    __shared__ float kf[KPB][128];
    __shared__ float h64[KPB][64];
    __shared__ float logit[KPB][3];
    __shared__ float swx[KPB][3];
    __shared__ float sF[KPB][260];
    __shared__ float sH[KPB][260];

    const int tid = threadIdx.x;
    const int w = tid >> 5, lane = tid & 31;
    const int g0 = blockIdx.x * KPB;

    if (w >= 4) {
        // ---- phase 1 (warps 4-7): kf gather — 2x128 = 256 elements
        int t = tid - 128;               // 0..127
        #pragma unroll
        for (int q = 0; q < 2; ++q) {
            int idx = t + q * 128;
            int k = idx >> 7, c = idx & 127;
            int g = g0 + k;
            int b = g / NKEY;
            int ki = g_topk[g];
            kf[k][c] = fusion_feat[((size_t)b * NF + ki) * C + c];
        }
    } else {
        // ---- phase 1 (warps 0-3): knn. warp w -> key g0+(w>>1), src w&1 ----
        const int klocal = w >> 1;
        const int src = w & 1;
        const int g = g0 + klocal;
        const int b = g / NKEY;
        float2 kw = g_keyworld[g];
        const float kx = kw.x, ky = kw.y;
        const float r2 = (src == 0) ? 5.76f : 23.04f;
        const float cell = (src == 0) ? CELL0 : CELL1;
        const int dim = (src == 0) ? DIM0 : DIM1;
        int cx = min(dim - 1, max(0, (int)floorf((kx + 54.0f) / cell)));
        int cy = min(dim - 1, max(0, (int)floorf((ky + 54.0f) / cell)));

        const int* ccnt = g_cellcnt[src][b];
        const float4* cpts = g_cellpts[src][b];

        int cids[9];
        int cnts[9];
        int ncell = 0;
        #pragma unroll
        for (int dy = -1; dy <= 1; ++dy) {
            int yy = cy + dy;
            if (yy < 0 || yy >= dim) continue;
            #pragma unroll
            for (int dx = -1; dx <= 1; ++dx) {
                int xx = cx + dx;
                if (xx < 0 || xx >= dim) continue;
                int cid = yy * dim + xx;
                cids[ncell] = cid;
                cnts[ncell] = min(ccnt[cid], CAP);
                ++ncell;
            }
        }

        unsigned long long lst[16];
        #pragma unroll
        for (int q = 0; q < 16; ++q) lst[q] = SENT;

        for (int cc = 0; cc < ncell; ++cc) {
            const int e = cnts[cc];
            const float4* cp = cpts + cids[cc] * CAP;
            for (int i = lane; i < e; i += 32) {
                float4 p = cp[i];
                float ddx = kx - p.x;
                float ddy = ky - p.y;
                float d2 = __fadd_rn(__fmul_rn(ddx, ddx), __fmul_rn(ddy, ddy));
                if (d2 <= r2) {
                    unsigned long long kk =
                        ((unsigned long long)__float_as_uint(d2) << 32) |
                        (unsigned long long)__float_as_uint(p.z);
                    if (kk < lst[15]) {
                        unsigned long long cur = kk;
                        #pragma unroll
                        for (int q = 0; q < 16; ++q) {
                            unsigned long long mn = lst[q] < cur ? lst[q] : cur;
                            cur = lst[q] < cur ? cur : lst[q];
                            lst[q] = mn;
                        }
                    }
                }
            }
        }

        // warp merge: 16 globally-smallest keys into static registers
        unsigned nIdx[16];
        #pragma unroll
        for (int r = 0; r < 16; ++r) {
            unsigned long long mine = lst[0];
            unsigned long long best = mine;
            #pragma unroll
            for (int o = 16; o; o >>= 1) {
                unsigned long long other = __shfl_xor_sync(0xffffffffu, best, o);
                best = other < best ? other : best;
            }
            unsigned msk = __ballot_sync(0xffffffffu, mine == best);
            if (lane == __ffs((int)msk) - 1) {
                #pragma unroll
                for (int q = 0; q < 15; ++q) lst[q] = lst[q + 1];
                lst[15] = SENT;
            }
            nIdx[r] = (best == SENT) ? INVIDX : (unsigned)(best & 0xFFFFFFFFull);
        }

        // batched gather: 16 independent feature-row loads in flight
        const float* feat = ((src == 0) ? fa : fb) + (size_t)b * NS * C;
        float4 acc = make_float4(0.f, 0.f, 0.f, 0.f);
        #pragma unroll
        for (int r = 0; r < 16; ++r) {
            unsigned idx = nIdx[r];
            unsigned safe = (idx == INVIDX) ? 0u : idx;
            float ww = (idx == INVIDX) ? 0.f : __ldg(&knn_w[src * 16 + r]);
            float4 v = *(const float4*)(feat + (size_t)safe * C + lane * 4);
            acc.x += ww * v.x; acc.y += ww * v.y; acc.z += ww * v.z; acc.w += ww * v.w;
        }
        float bb = knn_b[src];
        float* dst = &smf[src][klocal][lane * 4];
        dst[0] = acc.x + bb; dst[1] = acc.y + bb; dst[2] = acc.z + bb; dst[3] = acc.w + bb;
    }
    __syncthreads();

    // ---- phase 2: kw MLP (2x128 @ 128x64), logits, softmax, fused build ----
    if (tid < 128) {
        int k = tid >> 6, j = tid & 63;
        float a = 0.f;
        #pragma unroll 8
        for (int i = 0; i < 128; ++i) a += kf[k][i] * __ldg(&kw1[i * 64 + j]);
        a = a * kg1[j] + kb1[j];
        h64[k][j] = a > 0.f ? a : 0.f;
    }
    __syncthreads();
    if (tid < 6) {
        int k = tid / 3, j = tid - k * 3;
        float a = 0.f;
        #pragma unroll 8
        for (int i = 0; i < 64; ++i) a += h64[k][i] * kw2[i * 3 + j];
        logit[k][j] = a + kb2[j];
    }
    __syncthreads();
    if (tid < KPB) {
        float l0 = logit[tid][0], l1 = logit[tid][1], l2 = logit[tid][2];
        float m = fmaxf(l0, fmaxf(l1, l2));
        float e0 = expf(l0 - m), e1 = expf(l1 - m), e2 = expf(l2 - m);
        float s = e0 + e1 + e2;
        swx[tid][0] = e0 / s; swx[tid][1] = e1 / s; swx[tid][2] = e2 / s;
    }
    __syncthreads();
    {
        int k = tid >> 7, c = tid & 127;
        float x = kf[k][c];
        float kv = swx[k][0] * x;
        float fs = kv * smf[0][k][c];
        kv = swx[k][1] * kv;
        fs += kv * smf[1][k][c];
        sF[k][c] = fs;
        sF[k][128 + c] = kv;
    }
    __syncthreads();

    // ---- phase 3a: H = relu((sF @ fw1)*g + b)  [2x256 @ 256x256] ----
    {
        const int c = tid;                 // one column per thread
        float a0 = 0.f, a1 = 0.f;
        #pragma unroll 8
        for (int i = 0; i < 256; ++i) {
            float wv = __ldg(&fw1[i * 256 + c]);
            a0 += sF[0][i] * wv;
            a1 += sF[1][i] * wv;
        }
        const float gg = fg1[c], bb = fb1[c];
        float h0 = a0 * gg + bb, h1 = a1 * gg + bb;
        sH[0][c] = h0 > 0.f ? h0 : 0.f;
        sH[1][c] = h1 > 0.f ? h1 : 0.f;
    }
    __syncthreads();

    // ---- phase 3b: out = sH @ fw2 + b2  [2x256 @ 256x128] ----
    {
        const int c = tid & 127, r = tid >> 7;   // 2 rows, 1 output/thread
        float a = 0.f;
        #pragma unroll 8
        for (int i = 0; i < 256; ++i)
            a += sH[r][i] * __ldg(&fw2[i * 128 + c]);
        outF[OUT_OFF + (size_t)(g0 + r) * 128 + c] = a + fb2[c];
    }
}

// ---------------- launch ----------------
extern "C" void kernel_launch(void* const* d_in, const int* in_sizes, int n_in,
                              void* d_out, int out_size)
{
    const float* fusion_feat = (const float*)d_in[0];
    const float* src_feat_a  = (const float*)d_in[1];
    const float* src_feat_b  = (const float*)d_in[2];
    const float* heat_w1 = (const float*)d_in[3];
    const float* heat_g1 = (const float*)d_in[4];
    const float* heat_b1 = (const float*)d_in[5];
    const float* heat_w2 = (const float*)d_in[6];
    const float* heat_b2 = (const float*)d_in[7];
    const float* knn_w = (const float*)d_in[8];
    const float* knn_b = (const float*)d_in[9];
    const float* kw_w1 = (const float*)d_in[10];
    const float* kw_g1 = (const float*)d_in[11];
    const float* kw_b1 = (const float*)d_in[12];
    const float* kw_w2 = (const float*)d_in[13];
    const float* kw_b2 = (const float*)d_in[14];
    const float* fuse_w1 = (const float*)d_in[15];
    const float* fuse_g1 = (const float*)d_in[16];
    const float* fuse_b1 = (const float*)d_in[17];
    const float* fuse_w2 = (const float*)d_in[18];
    const float* fuse_b2 = (const float*)d_in[19];
    const int* fusion_coords = (const int*)d_in[20];
    const int* src_coords_a  = (const int*)d_in[21];
    const int* src_coords_b  = (const int*)d_in[22];
    float* outF = (float*)d_out;

    cudaFuncSetAttribute(heat_kernel, cudaFuncAttributeMaxDynamicSharedMemorySize, HEAT_SMEM);
    cudaFuncSetAttribute(topk_kernel, cudaFuncAttributeMaxDynamicSharedMemorySize, TOPK_SMEM);

    cellreset_kernel<<<(2 * B * NCELLMAX + 1023) / 1024, 1024>>>();
    heat_kernel<<<NROWS / 64, 256, HEAT_SMEM>>>(fusion_feat, heat_w1, heat_g1,
                                                heat_b1, heat_w2, heat_b2,
                                                src_coords_a, src_coords_b, outF);
    topk_kernel<<<B, 1024, TOPK_SMEM>>>(fusion_coords, outF);
    megafuse_kernel<<<NK_TOT / KPB, 256>>>(src_feat_a, src_feat_b, knn_w, knn_b,
                                           fusion_feat, kw_w1, kw_g1, kw_b1,
                                           kw_w2, kw_b2, fuse_w1, fuse_g1,
                                           fuse_b1, fuse_w2, fuse_b2, outF);
}

// round 16
// speedup vs baseline: 1.2113x; 1.2113x over previous
#include <cuda_runtime.h>
#include <math.h>

#define B 2
#define NF 20000
#define NS 30000
#define C 128
#define NKEY 500
#define NROWS (B*NF)
#define NK_TOT (B*NKEY)   // 1000

// output layout (flattened, float32, in reference return order)
#define OUT_OFF  0        // (1000,128)
#define KVI_OFF  128000   // (1000,3)
#define HEAT_OFF 131000   // (40000,)
#define S10_OFF  171000   // (40000,10)
#define KC_OFF   571000   // (1000,)

// spatial binning params (cell > radius with wide margin -> 3x3 ring suffices)
#define DIM0 36
#define CELL0 3.0f
#define DIM1 22
#define CELL1 5.0f
#define NCELLMAX (DIM0*DIM0)   // 1296
#define CAP 192                // fixed per-cell capacity (avg 23 / 62; huge margin)

#define SENT 0xFFFFFFFFFFFFFFFFull
#define INVIDX 0xFFFFFFFFu

// ---------------- f32x2 packed-FMA helpers (sm_103a FFMA2) ----------------
__device__ __forceinline__ unsigned long long bcast2(float x) {
    unsigned long long r;
    asm("mov.b64 %0, {%1, %1};" : "=l"(r) : "f"(x));
    return r;
}
__device__ __forceinline__ unsigned long long pk2(float lo, float hi) {
    unsigned long long r;
    asm("mov.b64 %0, {%1, %2};" : "=l"(r) : "f"(lo), "f"(hi));
    return r;
}
__device__ __forceinline__ void fma2(unsigned long long &d,
                                     unsigned long long a, unsigned long long b) {
    asm("fma.rn.f32x2 %0, %1, %2, %0;" : "+l"(d) : "l"(a), "l"(b));
}
__device__ __forceinline__ float2 up2(unsigned long long v) {
    float lo, hi;
    asm("mov.b64 {%0, %1}, %2;" : "=f"(lo), "=f"(hi) : "l"(v));
    return make_float2(lo, hi);
}

// ---------------- scratch (device globals; no allocs allowed) ----------------
__device__ float g_sig[NROWS];
__device__ int   g_cls[NROWS];
__device__ int   g_topk[NK_TOT];
__device__ float2 g_keyworld[NK_TOT];
__device__ int    g_cellcnt[2][B][NCELLMAX];
__device__ float4 g_cellpts[2][B][NCELLMAX*CAP];   // {wx, wy, idx-bits, 0}

__device__ __forceinline__ float worldc(int c, float stride) {
    float t = __fadd_rn((float)c, 0.5f);
    t = __fmul_rn(t, stride);
    t = __fmul_rn(t, 0.075f);
    return __fadd_rn(t, -54.0f);
}

// ---------------- K0: zero cell counts (before this call's bin build) --------
__global__ void cellreset_kernel() {
    int i = blockIdx.x * 1024 + threadIdx.x;
    if (i < 2 * B * NCELLMAX) ((int*)g_cellcnt)[i] = 0;
}

// ---------------- K1: heat MLP (40000 x 128 -> 128 relu -> 10) ----------------
#define SXS 132
#define HEAT_SMEM ((64*SXS + 128*12 + 64*10) * 4)
#define BIN_PER_BLOCK 192   // 625 blocks * 192 = 120000 = 2*B*NS exactly

__global__ void __launch_bounds__(256) heat_kernel(
    const float* __restrict__ X, const float* __restrict__ W1,
    const float* __restrict__ G1, const float* __restrict__ B1,
    const float* __restrict__ W2, const float* __restrict__ B2v,
    const int* __restrict__ ca, const int* __restrict__ cb,
    float* __restrict__ outF)
{
    extern __shared__ float sm[];
    float* sX  = sm;                     // 64 * SXS
    float* sW2 = sm + 64 * SXS;          // 128 * 12
    float* sS  = sW2 + 128 * 12;         // 64 * 10
    const int tid = threadIdx.x;
    const int rowbase = blockIdx.x * 64;

    // ---- bin-build prologue ----
    if (tid < BIN_PER_BLOCK) {
        int id = blockIdx.x * BIN_PER_BLOCK + tid;
        int src = id / (B * NS);
        int rem = id - src * (B * NS);
        int b = rem / NS, i = rem - b * NS;
        int2 cc = ((const int2*)(src == 0 ? ca : cb))[b * NS + i];
        float stride = (src == 0) ? 4.0f : 8.0f;
        float wx = worldc(cc.x, stride), wy = worldc(cc.y, stride);
        float cell = (src == 0) ? CELL0 : CELL1;
        int dim = (src == 0) ? DIM0 : DIM1;
        int cx = min(dim - 1, max(0, (int)floorf((wx + 54.0f) / cell)));
        int cy = min(dim - 1, max(0, (int)floorf((wy + 54.0f) / cell)));
        int cid = cy * dim + cx;
        int pos = atomicAdd(&g_cellcnt[src][b][cid], 1);
        if (pos < CAP)
            g_cellpts[src][b][cid * CAP + pos] =
                make_float4(wx, wy, __uint_as_float((unsigned)i), 0.f);
    }

    {
        const float4* s = (const float4*)(X + (size_t)rowbase * C);
        #pragma unroll
        for (int t = 0; t < 8; ++t) {
            int idx = tid + t * 256;
            int row = idx >> 5, c4 = idx & 31;
            *(float4*)(sX + row * SXS + c4 * 4) = s[idx];
        }
    }
    for (int t = tid; t < 128 * 12; t += 256) {
        int i = t / 12, c = t - i * 12;
        sW2[t] = (c < 10) ? W2[i * 10 + c] : 0.f;
    }
    __syncthreads();

    const int ty = tid >> 4, tx = tid & 15;
    const int r0 = ty * 4, c0 = tx * 8;
    // packed accumulators: acc2[i][jp] holds cols (2jp, 2jp+1) of row r0+i
    unsigned long long acc2[4][4];
    #pragma unroll
    for (int i = 0; i < 4; ++i)
        #pragma unroll
        for (int j = 0; j < 4; ++j) acc2[i][j] = 0ull;

    #pragma unroll 2
    for (int k = 0; k < 128; k += 4) {
        // weight rows: the float4 bits ARE the packed f32x2 operands
        ulonglong2 wa[4], wb[4];
        #pragma unroll
        for (int kk = 0; kk < 4; ++kk) {
            wa[kk] = __ldg((const ulonglong2*)(W1 + (k + kk) * 128 + c0));
            wb[kk] = __ldg((const ulonglong2*)(W1 + (k + kk) * 128 + c0 + 4));
        }
        float4 xr[4];
        #pragma unroll
        for (int i = 0; i < 4; ++i)
            xr[i] = *(const float4*)&sX[(r0 + i) * SXS + k];
        #pragma unroll
        for (int kk = 0; kk < 4; ++kk) {
            #pragma unroll
            for (int i = 0; i < 4; ++i) {
                float x = (kk == 0) ? xr[i].x : (kk == 1) ? xr[i].y
                        : (kk == 2) ? xr[i].z : xr[i].w;
                unsigned long long xb = bcast2(x);
                fma2(acc2[i][0], xb, wa[kk].x);
                fma2(acc2[i][1], xb, wa[kk].y);
                fma2(acc2[i][2], xb, wb[kk].x);
                fma2(acc2[i][3], xb, wb[kk].y);
            }
        }
    }
    float accf[4][8];
    #pragma unroll
    for (int i = 0; i < 4; ++i)
        #pragma unroll
        for (int jp = 0; jp < 4; ++jp) {
            float2 v = up2(acc2[i][jp]);
            accf[i][2 * jp] = v.x;
            accf[i][2 * jp + 1] = v.y;
        }
    float4 ga = *(const float4*)&G1[c0], gb = *(const float4*)&G1[c0 + 4];
    float4 ba = *(const float4*)&B1[c0], bb = *(const float4*)&B1[c0 + 4];
    float gv[8] = {ga.x, ga.y, ga.z, ga.w, gb.x, gb.y, gb.z, gb.w};
    float bv[8] = {ba.x, ba.y, ba.z, ba.w, bb.x, bb.y, bb.z, bb.w};
    __syncthreads();
    #pragma unroll
    for (int i = 0; i < 4; ++i)
        #pragma unroll
        for (int j = 0; j < 8; ++j) {
            float h = accf[i][j] * gv[j] + bv[j];
            sX[(r0 + i) * SXS + c0 + j] = h > 0.f ? h : 0.f;
        }
    __syncthreads();

    if (tid < 128) {
        const int r = tid >> 1, hhalf = tid & 1;
        const int cc0 = hhalf * 5;
        float a[5] = {0.f, 0.f, 0.f, 0.f, 0.f};
        for (int i = 0; i < 128; ++i) {
            float hv = sX[r * SXS + i];
            #pragma unroll
            for (int q = 0; q < 5; ++q) a[q] += hv * sW2[i * 12 + cc0 + q];
        }
        #pragma unroll
        for (int q = 0; q < 5; ++q) {
            int c = cc0 + q;
            float v = a[q] + B2v[c];
            outF[S10_OFF + (size_t)(rowbase + r) * 10 + c] = v;
            sS[r * 10 + c] = v;
        }
    }
    __syncthreads();
    if (tid < 64) {
        int r = tid, row = rowbase + r;
        float m = -INFINITY; int a = 0;
        #pragma unroll
        for (int c = 0; c < 10; ++c) {
            float v = sS[r * 10 + c];
            if (v > m) { m = v; a = c; }
        }
        outF[HEAT_OFF + row] = m;
        g_sig[row] = 1.f / (1.f + expf(-m));
        g_cls[row] = a;
    }
}

// ---------------- K2: per-batch top-500 (jax.lax.top_k semantics) ----------------
#define VPT 20
#define CANDMAX 2048
#define TOPK_SMEM (CANDMAX * 8)

__global__ void __launch_bounds__(1024) topk_kernel(
    const int* __restrict__ fusion_coords, float* __restrict__ outF)
{
    extern __shared__ unsigned char dsm[];
    unsigned long long* cand = (unsigned long long*)dsm;
    __shared__ int s_cnt[32];
    __shared__ int s_n;
    const int tid = threadIdx.x;
    const int lane = tid & 31;
    const int b = blockIdx.x;

    unsigned vals[VPT];
    #pragma unroll
    for (int t = 0; t < VPT; ++t) {
        int i = tid + t * 1024;
        vals[t] = (i < NF) ? __float_as_uint(g_sig[b * NF + i]) : 0u;
    }
    if (tid < 32) s_cnt[tid] = 0;
    if (tid == 0) s_n = 0;
    cand[tid] = 0ull;
    cand[tid + 1024] = 0ull;
    __syncthreads();

    unsigned lo = 0u, hi = 0x3F800000u;
    #pragma unroll 1
    for (int it = 0; it < 31; ++it) {
        unsigned mid = lo + ((hi - lo) >> 1);
        int c = 0;
        #pragma unroll
        for (int t = 0; t < VPT; ++t) c += (vals[t] >= mid) ? 1 : 0;
        #pragma unroll
        for (int o = 16; o; o >>= 1) c += __shfl_xor_sync(0xffffffffu, c, o);
        if (lane == 0 && c) atomicAdd(&s_cnt[it], c);
        __syncthreads();
        if (s_cnt[it] >= NKEY) lo = mid; else hi = mid;
    }
    const unsigned thr = lo;

    #pragma unroll
    for (int t = 0; t < VPT; ++t) {
        unsigned v = vals[t];
        if (v >= thr) {
            int i = tid + t * 1024;
            int p = atomicAdd(&s_n, 1);
            if (p < CANDMAX)
                cand[p] = ((unsigned long long)v << 32) |
                          (unsigned long long)(0xFFFFFFFFu - (unsigned)i);
        }
    }
    __syncthreads();
    int n = s_n; if (n > CANDMAX) n = CANDMAX;

    for (int s = tid; s < CANDMAX; s += 1024) {
        unsigned long long mine = cand[s];
        if (mine == 0ull || s >= n) continue;
        int rank = 0;
        for (int j = 0; j < n; ++j) rank += (cand[j] > mine) ? 1 : 0;
        if (rank < NKEY) {
            unsigned idx = 0xFFFFFFFFu - (unsigned)(mine & 0xFFFFFFFFull);
            g_topk[b * NKEY + rank] = (int)idx;
            int2 cc = ((const int2*)fusion_coords)[b * NF + (int)idx];
            int o = (b * NKEY + rank) * 3;
            outF[KVI_OFF + o + 0] = (float)b;
            outF[KVI_OFF + o + 1] = (float)cc.x;
            outF[KVI_OFF + o + 2] = (float)cc.y;
            g_keyworld[b * NKEY + rank] = make_float2(worldc(cc.x, 8.0f), worldc(cc.y, 8.0f));
            outF[KC_OFF + b * NKEY + rank] = (float)g_cls[b * NF + (int)idx];
        }
    }
}

// ---------------- K3: MEGAFUSE — 4 keys/block, grid 250, 512 threads ---------
#define KPB 4   // keys per block

__global__ void __launch_bounds__(512) megafuse_kernel(
    const float* __restrict__ fa, const float* __restrict__ fb,
    const float* __restrict__ knn_w, const float* __restrict__ knn_b,
    const float* __restrict__ fusion_feat,
    const float* __restrict__ kw1, const float* __restrict__ kg1,
    const float* __restrict__ kb1, const float* __restrict__ kw2,
    const float* __restrict__ kb2,
    const float* __restrict__ fw1, const float* __restrict__ fg1,
    const float* __restrict__ fb1, const float* __restrict__ fw2,
    const float* __restrict__ fb2, float* __restrict__ outF)
{
    __shared__ float smf[2][KPB][128];
    __shared__ float kf[KPB][128];
    __shared__ float h64[KPB][64];
    __shared__ float logit[KPB][3];
    __shared__ float swx[KPB][3];
    __shared__ __align__(16) float sFt[256][4];   // TRANSPOSED fused: [col][row]
    __shared__ float pH[2][KPB][260];             // k-split partials
    __shared__ __align__(16) float sH[KPB][260];

    const int tid = threadIdx.x;
    const int w = tid >> 5, lane = tid & 31;
    const int g0 = blockIdx.x * KPB;

    if (w >= 8) {
        // ---- phase 1 (warps 8-15): kf gather — 4x128 = 512 elements
        int t = (w - 8) * 32 + lane;
        #pragma unroll
        for (int q = 0; q < 2; ++q) {
            int idx = t + q * 256;
            int k = idx >> 7, c = idx & 127;
            int g = g0 + k;
            int b = g / NKEY;
            int ki = g_topk[g];
            kf[k][c] = fusion_feat[((size_t)b * NF + ki) * C + c];
        }
    } else {
        // ---- phase 1 (warps 0-7): knn. warp w -> key g0+(w>>1), src w&1 ----
        const int klocal = w >> 1;
        const int src = w & 1;
        const int g = g0 + klocal;
        const int b = g / NKEY;
        float2 kw = g_keyworld[g];
        const float kx = kw.x, ky = kw.y;
        const float r2 = (src == 0) ? 5.76f : 23.04f;
        const float cell = (src == 0) ? CELL0 : CELL1;
        const int dim = (src == 0) ? DIM0 : DIM1;
        int cx = min(dim - 1, max(0, (int)floorf((kx + 54.0f) / cell)));
        int cy = min(dim - 1, max(0, (int)floorf((ky + 54.0f) / cell)));

        const int* ccnt = g_cellcnt[src][b];
        const float4* cpts = g_cellpts[src][b];

        int cids[9];
        int cnts[9];
        int ncell = 0;
        #pragma unroll
        for (int dy = -1; dy <= 1; ++dy) {
            int yy = cy + dy;
            if (yy < 0 || yy >= dim) continue;
            #pragma unroll
            for (int dx = -1; dx <= 1; ++dx) {
                int xx = cx + dx;
                if (xx < 0 || xx >= dim) continue;
                int cid = yy * dim + xx;
                cids[ncell] = cid;
                cnts[ncell] = min(ccnt[cid], CAP);
                ++ncell;
            }
        }

        unsigned long long lst[16];
        #pragma unroll
        for (int q = 0; q < 16; ++q) lst[q] = SENT;

        for (int cc = 0; cc < ncell; ++cc) {
            const int e = cnts[cc];
            const float4* cp = cpts + cids[cc] * CAP;
            for (int i = lane; i < e; i += 32) {
                float4 p = cp[i];
                float ddx = kx - p.x;
                float ddy = ky - p.y;
                float d2 = __fadd_rn(__fmul_rn(ddx, ddx), __fmul_rn(ddy, ddy));
                if (d2 <= r2) {
                    unsigned long long kk =
                        ((unsigned long long)__float_as_uint(d2) << 32) |
                        (unsigned long long)__float_as_uint(p.z);
                    if (kk < lst[15]) {
                        unsigned long long cur = kk;
                        #pragma unroll
                        for (int q = 0; q < 16; ++q) {
                            unsigned long long mn = lst[q] < cur ? lst[q] : cur;
                            cur = lst[q] < cur ? cur : lst[q];
                            lst[q] = mn;
                        }
                    }
                }
            }
        }

        // warp merge: 16 globally-smallest keys into static registers
        unsigned nIdx[16];
        #pragma unroll
        for (int r = 0; r < 16; ++r) {
            unsigned long long mine = lst[0];
            unsigned long long best = mine;
            #pragma unroll
            for (int o = 16; o; o >>= 1) {
                unsigned long long other = __shfl_xor_sync(0xffffffffu, best, o);
                best = other < best ? other : best;
            }
            unsigned msk = __ballot_sync(0xffffffffu, mine == best);
            if (lane == __ffs((int)msk) - 1) {
                #pragma unroll
                for (int q = 0; q < 15; ++q) lst[q] = lst[q + 1];
                lst[15] = SENT;
            }
            nIdx[r] = (best == SENT) ? INVIDX : (unsigned)(best & 0xFFFFFFFFull);
        }

        // batched gather: 16 independent feature-row loads in flight
        const float* feat = ((src == 0) ? fa : fb) + (size_t)b * NS * C;
        float4 acc = make_float4(0.f, 0.f, 0.f, 0.f);
        #pragma unroll
        for (int r = 0; r < 16; ++r) {
            unsigned idx = nIdx[r];
            unsigned safe = (idx == INVIDX) ? 0u : idx;
            float ww = (idx == INVIDX) ? 0.f : __ldg(&knn_w[src * 16 + r]);
            float4 v = *(const float4*)(feat + (size_t)safe * C + lane * 4);
            acc.x += ww * v.x; acc.y += ww * v.y; acc.z += ww * v.z; acc.w += ww * v.w;
        }
        float bb = knn_b[src];
        float* dst = &smf[src][klocal][lane * 4];
        dst[0] = acc.x + bb; dst[1] = acc.y + bb; dst[2] = acc.z + bb; dst[3] = acc.w + bb;
    }
    __syncthreads();

    // ---- phase 2: kw MLP (4x128 @ 128x64), logits, softmax, fused build ----
    if (tid < 256) {
        int k = tid >> 6, j = tid & 63;
        float a = 0.f;
        #pragma unroll 8
        for (int i = 0; i < 128; ++i) a += kf[k][i] * __ldg(&kw1[i * 64 + j]);
        a = a * kg1[j] + kb1[j];
        h64[k][j] = a > 0.f ? a : 0.f;
    }
    __syncthreads();
    if (tid < 12) {
        int k = tid / 3, j = tid - k * 3;
        float a = 0.f;
        #pragma unroll 8
        for (int i = 0; i < 64; ++i) a += h64[k][i] * kw2[i * 3 + j];
        logit[k][j] = a + kb2[j];
    }
    __syncthreads();
    if (tid < KPB) {
        float l0 = logit[tid][0], l1 = logit[tid][1], l2 = logit[tid][2];
        float m = fmaxf(l0, fmaxf(l1, l2));
        float e0 = expf(l0 - m), e1 = expf(l1 - m), e2 = expf(l2 - m);
        float s = e0 + e1 + e2;
        swx[tid][0] = e0 / s; swx[tid][1] = e1 / s; swx[tid][2] = e2 / s;
    }
    __syncthreads();
    if (tid < 512) {
        int k = tid >> 7, c = tid & 127;
        float x = kf[k][c];
        float kv = swx[k][0] * x;
        float fs = kv * smf[0][k][c];
        kv = swx[k][1] * kv;
        fs += kv * smf[1][k][c];
        sFt[c][k] = fs;            // transposed store: [col][row]
        sFt[128 + c][k] = kv;
    }
    __syncthreads();

    // ---- phase 3a: partial H over k-halves, packed f32x2 ----
    {
        const int kh = tid >> 8;           // 0/1 -> i in [kh*128, kh*128+128)
        const int c = tid & 255;
        const int ib = kh * 128;
        unsigned long long a01 = 0ull, a23 = 0ull;   // rows (0,1) and (2,3)
        #pragma unroll 8
        for (int i = 0; i < 128; ++i) {
            float wv = __ldg(&fw1[(ib + i) * 256 + c]);
            unsigned long long wp = bcast2(wv);
            ulonglong2 xv = *(const ulonglong2*)&sFt[ib + i][0];
            fma2(a01, xv.x, wp);
            fma2(a23, xv.y, wp);
        }
        float2 v01 = up2(a01), v23 = up2(a23);
        pH[kh][0][c] = v01.x; pH[kh][1][c] = v01.y;
        pH[kh][2][c] = v23.x; pH[kh][3][c] = v23.y;
    }
    __syncthreads();
    // combine + BN + ReLU: 1024 outputs over 512 threads
    #pragma unroll
    for (int q = 0; q < 2; ++q) {
        int idx = tid + q * 512;
        int r = idx >> 8, c = idx & 255;
        float h = (pH[0][r][c] + pH[1][r][c]) * fg1[c] + fb1[c];
        sH[r][c] = h > 0.f ? h : 0.f;
    }
    __syncthreads();

    // ---- phase 3b: out = sH @ fw2 + b2, packed over i-pairs ----
    {
        const int c = tid & 127, r = tid >> 7;   // 4 rows, 1 output/thread
        unsigned long long acc = 0ull;
        #pragma unroll 4
        for (int q = 0; q < 128; ++q) {
            float w0 = __ldg(&fw2[(2 * q) * 128 + c]);
            float w1 = __ldg(&fw2[(2 * q + 1) * 128 + c]);
            unsigned long long wp = pk2(w0, w1);
            unsigned long long xv = *(const unsigned long long*)&sH[r][2 * q];
            fma2(acc, xv, wp);
        }
        float2 v = up2(acc);
        outF[OUT_OFF + (size_t)(g0 + r) * 128 + c] = v.x + v.y + fb2[c];
    }
}

// ---------------- launch ----------------
extern "C" void kernel_launch(void* const* d_in, const int* in_sizes, int n_in,
                              void* d_out, int out_size)
{
    const float* fusion_feat = (const float*)d_in[0];
    const float* src_feat_a  = (const float*)d_in[1];
    const float* src_feat_b  = (const float*)d_in[2];
    const float* heat_w1 = (const float*)d_in[3];
    const float* heat_g1 = (const float*)d_in[4];
    const float* heat_b1 = (const float*)d_in[5];
    const float* heat_w2 = (const float*)d_in[6];
    const float* heat_b2 = (const float*)d_in[7];
    const float* knn_w = (const float*)d_in[8];
    const float* knn_b = (const float*)d_in[9];
    const float* kw_w1 = (const float*)d_in[10];
    const float* kw_g1 = (const float*)d_in[11];
    const float* kw_b1 = (const float*)d_in[12];
    const float* kw_w2 = (const float*)d_in[13];
    const float* kw_b2 = (const float*)d_in[14];
    const float* fuse_w1 = (const float*)d_in[15];
    const float* fuse_g1 = (const float*)d_in[16];
    const float* fuse_b1 = (const float*)d_in[17];
    const float* fuse_w2 = (const float*)d_in[18];
    const float* fuse_b2 = (const float*)d_in[19];
    const int* fusion_coords = (const int*)d_in[20];
    const int* src_coords_a  = (const int*)d_in[21];
    const int* src_coords_b  = (const int*)d_in[22];
    float* outF = (float*)d_out;

    cudaFuncSetAttribute(heat_kernel, cudaFuncAttributeMaxDynamicSharedMemorySize, HEAT_SMEM);
    cudaFuncSetAttribute(topk_kernel, cudaFuncAttributeMaxDynamicSharedMemorySize, TOPK_SMEM);

    cellreset_kernel<<<(2 * B * NCELLMAX + 1023) / 1024, 1024>>>();
    heat_kernel<<<NROWS / 64, 256, HEAT_SMEM>>>(fusion_feat, heat_w1, heat_g1,
                                                heat_b1, heat_w2, heat_b2,
                                                src_coords_a, src_coords_b, outF);
    topk_kernel<<<B, 1024, TOPK_SMEM>>>(fusion_coords, outF);
    megafuse_kernel<<<NK_TOT / KPB, 512>>>(src_feat_a, src_feat_b, knn_w, knn_b,
                                           fusion_feat, kw_w1, kw_g1, kw_b1,
                                           kw_w2, kw_b2, fuse_w1, fuse_g1,
                                           fuse_b1, fuse_w2, fuse_b2, outF);
}

// round 17
// speedup vs baseline: 1.2301x; 1.0156x over previous
#include <cuda_runtime.h>
#include <math.h>

#define B 2
#define NF 20000
#define NS 30000
#define C 128
#define NKEY 500
#define NROWS (B*NF)
#define NK_TOT (B*NKEY)   // 1000

// output layout (flattened, float32, in reference return order)
#define OUT_OFF  0        // (1000,128)
#define KVI_OFF  128000   // (1000,3)
#define HEAT_OFF 131000   // (40000,)
#define S10_OFF  171000   // (40000,10)
#define KC_OFF   571000   // (1000,)

// spatial binning params (cell > radius with wide margin -> 3x3 ring suffices)
#define DIM0 36
#define CELL0 3.0f
#define DIM1 22
#define CELL1 5.0f
#define NCELLMAX (DIM0*DIM0)   // 1296
#define CAP 192                // fixed per-cell capacity (avg 23 / 62; huge margin)

#define SENT 0xFFFFFFFFFFFFFFFFull
#define INVIDX 0xFFFFFFFFu

// ---------------- f32x2 packed-FMA helpers (sm_103a FFMA2) ----------------
__device__ __forceinline__ unsigned long long bcast2(float x) {
    unsigned long long r;
    asm("mov.b64 %0, {%1, %1};" : "=l"(r) : "f"(x));
    return r;
}
__device__ __forceinline__ unsigned long long pk2(float lo, float hi) {
    unsigned long long r;
    asm("mov.b64 %0, {%1, %2};" : "=l"(r) : "f"(lo), "f"(hi));
    return r;
}
__device__ __forceinline__ void fma2(unsigned long long &d,
                                     unsigned long long a, unsigned long long b) {
    asm("fma.rn.f32x2 %0, %1, %2, %0;" : "+l"(d) : "l"(a), "l"(b));
}
__device__ __forceinline__ float2 up2(unsigned long long v) {
    float lo, hi;
    asm("mov.b64 {%0, %1}, %2;" : "=f"(lo), "=f"(hi) : "l"(v));
    return make_float2(lo, hi);
}

// ---------------- scratch (device globals; no allocs allowed) ----------------
__device__ float g_sig[NROWS];
__device__ int   g_cls[NROWS];
__device__ int   g_topk[NK_TOT];
__device__ float2 g_keyworld[NK_TOT];
__device__ int    g_cellcnt[2][B][NCELLMAX];
__device__ float4 g_cellpts[2][B][NCELLMAX*CAP];   // {wx, wy, idx-bits, 0}

__device__ __forceinline__ float worldc(int c, float stride) {
    float t = __fadd_rn((float)c, 0.5f);
    t = __fmul_rn(t, stride);
    t = __fmul_rn(t, 0.075f);
    return __fadd_rn(t, -54.0f);
}

// ---------------- K0: zero cell counts (before this call's bin build) --------
__global__ void cellreset_kernel() {
    int i = blockIdx.x * 1024 + threadIdx.x;
    if (i < 2 * B * NCELLMAX) ((int*)g_cellcnt)[i] = 0;
}

// ---------------- K1: heat MLP (40000 x 128 -> 128 relu -> 10) ----------------
#define SXS 132
#define HEAT_SMEM ((64*SXS + 128*12 + 64*10) * 4)
#define BIN_PER_BLOCK 192   // 625 blocks * 192 = 120000 = 2*B*NS exactly

__global__ void __launch_bounds__(256) heat_kernel(
    const float* __restrict__ X, const float* __restrict__ W1,
    const float* __restrict__ G1, const float* __restrict__ B1,
    const float* __restrict__ W2, const float* __restrict__ B2v,
    const int* __restrict__ ca, const int* __restrict__ cb,
    float* __restrict__ outF)
{
    extern __shared__ float sm[];
    float* sX  = sm;                     // 64 * SXS
    float* sW2 = sm + 64 * SXS;          // 128 * 12
    float* sS  = sW2 + 128 * 12;         // 64 * 10
    const int tid = threadIdx.x;
    const int rowbase = blockIdx.x * 64;

    // ---- bin-build prologue ----
    if (tid < BIN_PER_BLOCK) {
        int id = blockIdx.x * BIN_PER_BLOCK + tid;
        int src = id / (B * NS);
        int rem = id - src * (B * NS);
        int b = rem / NS, i = rem - b * NS;
        int2 cc = ((const int2*)(src == 0 ? ca : cb))[b * NS + i];
        float stride = (src == 0) ? 4.0f : 8.0f;
        float wx = worldc(cc.x, stride), wy = worldc(cc.y, stride);
        float cell = (src == 0) ? CELL0 : CELL1;
        int dim = (src == 0) ? DIM0 : DIM1;
        int cx = min(dim - 1, max(0, (int)floorf((wx + 54.0f) / cell)));
        int cy = min(dim - 1, max(0, (int)floorf((wy + 54.0f) / cell)));
        int cid = cy * dim + cx;
        int pos = atomicAdd(&g_cellcnt[src][b][cid], 1);
        if (pos < CAP)
            g_cellpts[src][b][cid * CAP + pos] =
                make_float4(wx, wy, __uint_as_float((unsigned)i), 0.f);
    }

    {
        const float4* s = (const float4*)(X + (size_t)rowbase * C);
        #pragma unroll
        for (int t = 0; t < 8; ++t) {
            int idx = tid + t * 256;
            int row = idx >> 5, c4 = idx & 31;
            *(float4*)(sX + row * SXS + c4 * 4) = s[idx];
        }
    }
    for (int t = tid; t < 128 * 12; t += 256) {
        int i = t / 12, c = t - i * 12;
        sW2[t] = (c < 10) ? W2[i * 10 + c] : 0.f;
    }
    __syncthreads();

    const int ty = tid >> 4, tx = tid & 15;
    const int r0 = ty * 4, c0 = tx * 8;
    unsigned long long acc2[4][4];
    #pragma unroll
    for (int i = 0; i < 4; ++i)
        #pragma unroll
        for (int j = 0; j < 4; ++j) acc2[i][j] = 0ull;

    #pragma unroll 2
    for (int k = 0; k < 128; k += 4) {
        ulonglong2 wa[4], wb[4];
        #pragma unroll
        for (int kk = 0; kk < 4; ++kk) {
            wa[kk] = __ldg((const ulonglong2*)(W1 + (k + kk) * 128 + c0));
            wb[kk] = __ldg((const ulonglong2*)(W1 + (k + kk) * 128 + c0 + 4));
        }
        float4 xr[4];
        #pragma unroll
        for (int i = 0; i < 4; ++i)
            xr[i] = *(const float4*)&sX[(r0 + i) * SXS + k];
        #pragma unroll
        for (int kk = 0; kk < 4; ++kk) {
            #pragma unroll
            for (int i = 0; i < 4; ++i) {
                float x = (kk == 0) ? xr[i].x : (kk == 1) ? xr[i].y
                        : (kk == 2) ? xr[i].z : xr[i].w;
                unsigned long long xb = bcast2(x);
                fma2(acc2[i][0], xb, wa[kk].x);
                fma2(acc2[i][1], xb, wa[kk].y);
                fma2(acc2[i][2], xb, wb[kk].x);
                fma2(acc2[i][3], xb, wb[kk].y);
            }
        }
    }
    float accf[4][8];
    #pragma unroll
    for (int i = 0; i < 4; ++i)
        #pragma unroll
        for (int jp = 0; jp < 4; ++jp) {
            float2 v = up2(acc2[i][jp]);
            accf[i][2 * jp] = v.x;
            accf[i][2 * jp + 1] = v.y;
        }
    float4 ga = *(const float4*)&G1[c0], gb = *(const float4*)&G1[c0 + 4];
    float4 ba = *(const float4*)&B1[c0], bb = *(const float4*)&B1[c0 + 4];
    float gv[8] = {ga.x, ga.y, ga.z, ga.w, gb.x, gb.y, gb.z, gb.w};
    float bv[8] = {ba.x, ba.y, ba.z, ba.w, bb.x, bb.y, bb.z, bb.w};
    __syncthreads();
    #pragma unroll
    for (int i = 0; i < 4; ++i)
        #pragma unroll
        for (int j = 0; j < 8; ++j) {
            float h = accf[i][j] * gv[j] + bv[j];
            sX[(r0 + i) * SXS + c0 + j] = h > 0.f ? h : 0.f;
        }
    __syncthreads();

    if (tid < 128) {
        const int r = tid >> 1, hhalf = tid & 1;
        const int cc0 = hhalf * 5;
        float a[5] = {0.f, 0.f, 0.f, 0.f, 0.f};
        for (int i = 0; i < 128; ++i) {
            float hv = sX[r * SXS + i];
            #pragma unroll
            for (int q = 0; q < 5; ++q) a[q] += hv * sW2[i * 12 + cc0 + q];
        }
        #pragma unroll
        for (int q = 0; q < 5; ++q) {
            int c = cc0 + q;
            float v = a[q] + B2v[c];
            outF[S10_OFF + (size_t)(rowbase + r) * 10 + c] = v;
            sS[r * 10 + c] = v;
        }
    }
    __syncthreads();
    if (tid < 64) {
        int r = tid, row = rowbase + r;
        float m = -INFINITY; int a = 0;
        #pragma unroll
        for (int c = 0; c < 10; ++c) {
            float v = sS[r * 10 + c];
            if (v > m) { m = v; a = c; }
        }
        outF[HEAT_OFF + row] = m;
        g_sig[row] = 1.f / (1.f + expf(-m));
        g_cls[row] = a;
    }
}

// ---------------- K2: per-batch top-500 (jax.lax.top_k semantics) ----------------
#define VPT 20
#define CANDMAX 2048
#define TOPK_SMEM (CANDMAX * 8)

__global__ void __launch_bounds__(1024) topk_kernel(
    const int* __restrict__ fusion_coords, float* __restrict__ outF)
{
    extern __shared__ unsigned char dsm[];
    unsigned long long* cand = (unsigned long long*)dsm;
    __shared__ int s_cnt[32];
    __shared__ int s_n;
    const int tid = threadIdx.x;
    const int lane = tid & 31;
    const int b = blockIdx.x;

    unsigned vals[VPT];
    #pragma unroll
    for (int t = 0; t < VPT; ++t) {
        int i = tid + t * 1024;
        vals[t] = (i < NF) ? __float_as_uint(g_sig[b * NF + i]) : 0u;
    }
    if (tid < 32) s_cnt[tid] = 0;
    if (tid == 0) s_n = 0;
    cand[tid] = 0ull;
    cand[tid + 1024] = 0ull;
    __syncthreads();

    unsigned lo = 0u, hi = 0x3F800000u;
    #pragma unroll 1
    for (int it = 0; it < 31; ++it) {
        unsigned mid = lo + ((hi - lo) >> 1);
        int c = 0;
        #pragma unroll
        for (int t = 0; t < VPT; ++t) c += (vals[t] >= mid) ? 1 : 0;
        #pragma unroll
        for (int o = 16; o; o >>= 1) c += __shfl_xor_sync(0xffffffffu, c, o);
        if (lane == 0 && c) atomicAdd(&s_cnt[it], c);
        __syncthreads();
        if (s_cnt[it] >= NKEY) lo = mid; else hi = mid;
    }
    const unsigned thr = lo;

    #pragma unroll
    for (int t = 0; t < VPT; ++t) {
        unsigned v = vals[t];
        if (v >= thr) {
            int i = tid + t * 1024;
            int p = atomicAdd(&s_n, 1);
            if (p < CANDMAX)
                cand[p] = ((unsigned long long)v << 32) |
                          (unsigned long long)(0xFFFFFFFFu - (unsigned)i);
        }
    }
    __syncthreads();
    int n = s_n; if (n > CANDMAX) n = CANDMAX;

    for (int s = tid; s < CANDMAX; s += 1024) {
        unsigned long long mine = cand[s];
        if (mine == 0ull || s >= n) continue;
        int rank = 0;
        for (int j = 0; j < n; ++j) rank += (cand[j] > mine) ? 1 : 0;
        if (rank < NKEY) {
            unsigned idx = 0xFFFFFFFFu - (unsigned)(mine & 0xFFFFFFFFull);
            g_topk[b * NKEY + rank] = (int)idx;
            int2 cc = ((const int2*)fusion_coords)[b * NF + (int)idx];
            int o = (b * NKEY + rank) * 3;
            outF[KVI_OFF + o + 0] = (float)b;
            outF[KVI_OFF + o + 1] = (float)cc.x;
            outF[KVI_OFF + o + 2] = (float)cc.y;
            g_keyworld[b * NKEY + rank] = make_float2(worldc(cc.x, 8.0f), worldc(cc.y, 8.0f));
            outF[KC_OFF + b * NKEY + rank] = (float)g_cls[b * NF + (int)idx];
        }
    }
}

// ---------------- K3: MEGAFUSE — 4 keys/block, grid 250, 512 threads ---------
#define KPB 4   // keys per block

__global__ void __launch_bounds__(512) megafuse_kernel(
    const float* __restrict__ fa, const float* __restrict__ fb,
    const float* __restrict__ knn_w, const float* __restrict__ knn_b,
    const float* __restrict__ fusion_feat,
    const float* __restrict__ kw1, const float* __restrict__ kg1,
    const float* __restrict__ kb1, const float* __restrict__ kw2,
    const float* __restrict__ kb2,
    const float* __restrict__ fw1, const float* __restrict__ fg1,
    const float* __restrict__ fb1, const float* __restrict__ fw2,
    const float* __restrict__ fb2, float* __restrict__ outF)
{
    __shared__ float smf[2][KPB][128];
    __shared__ float kf[KPB][128];
    __shared__ float h64[KPB][64];
    __shared__ float logit[KPB][3];
    __shared__ float swx[KPB][3];
    __shared__ __align__(16) float sFt[256][4];   // TRANSPOSED fused: [col][row]
    __shared__ float pH[2][KPB][260];             // fw1 k-split partials
    __shared__ __align__(16) float sHt[256][4];   // TRANSPOSED hidden: [col][row]
    __shared__ float pO[4][KPB][132];             // fw2 k-split partials

    const int tid = threadIdx.x;
    const int w = tid >> 5, lane = tid & 31;
    const int g0 = blockIdx.x * KPB;

    if (w >= 8) {
        // ---- phase 1 (warps 8-15): kf gather — 4x128 = 512 elements
        int t = (w - 8) * 32 + lane;
        #pragma unroll
        for (int q = 0; q < 2; ++q) {
            int idx = t + q * 256;
            int k = idx >> 7, c = idx & 127;
            int g = g0 + k;
            int b = g / NKEY;
            int ki = g_topk[g];
            kf[k][c] = fusion_feat[((size_t)b * NF + ki) * C + c];
        }
    } else {
        // ---- phase 1 (warps 0-7): knn. warp w -> key g0+(w>>1), src w&1 ----
        const int klocal = w >> 1;
        const int src = w & 1;
        const int g = g0 + klocal;
        const int b = g / NKEY;
        float2 kw = g_keyworld[g];
        const float kx = kw.x, ky = kw.y;
        const float r2 = (src == 0) ? 5.76f : 23.04f;
        const float cell = (src == 0) ? CELL0 : CELL1;
        const int dim = (src == 0) ? DIM0 : DIM1;
        int cx = min(dim - 1, max(0, (int)floorf((kx + 54.0f) / cell)));
        int cy = min(dim - 1, max(0, (int)floorf((ky + 54.0f) / cell)));

        const int* ccnt = g_cellcnt[src][b];
        const float4* cpts = g_cellpts[src][b];

        int cids[9];
        int cnts[9];
        int ncell = 0;
        #pragma unroll
        for (int dy = -1; dy <= 1; ++dy) {
            int yy = cy + dy;
            if (yy < 0 || yy >= dim) continue;
            #pragma unroll
            for (int dx = -1; dx <= 1; ++dx) {
                int xx = cx + dx;
                if (xx < 0 || xx >= dim) continue;
                int cid = yy * dim + xx;
                cids[ncell] = cid;
                cnts[ncell] = min(ccnt[cid], CAP);
                ++ncell;
            }
        }

        unsigned long long lst[16];
        #pragma unroll
        for (int q = 0; q < 16; ++q) lst[q] = SENT;

        for (int cc = 0; cc < ncell; ++cc) {
            const int e = cnts[cc];
            const float4* cp = cpts + cids[cc] * CAP;
            for (int i = lane; i < e; i += 32) {
                float4 p = cp[i];
                float ddx = kx - p.x;
                float ddy = ky - p.y;
                float d2 = __fadd_rn(__fmul_rn(ddx, ddx), __fmul_rn(ddy, ddy));
                if (d2 <= r2) {
                    unsigned long long kk =
                        ((unsigned long long)__float_as_uint(d2) << 32) |
                        (unsigned long long)__float_as_uint(p.z);
                    if (kk < lst[15]) {
                        unsigned long long cur = kk;
                        #pragma unroll
                        for (int q = 0; q < 16; ++q) {
                            unsigned long long mn = lst[q] < cur ? lst[q] : cur;
                            cur = lst[q] < cur ? cur : lst[q];
                            lst[q] = mn;
                        }
                    }
                }
            }
        }

        // warp merge: 16 globally-smallest keys into static registers
        unsigned nIdx[16];
        #pragma unroll
        for (int r = 0; r < 16; ++r) {
            unsigned long long mine = lst[0];
            unsigned long long best = mine;
            #pragma unroll
            for (int o = 16; o; o >>= 1) {
                unsigned long long other = __shfl_xor_sync(0xffffffffu, best, o);
                best = other < best ? other : best;
            }
            unsigned msk = __ballot_sync(0xffffffffu, mine == best);
            if (lane == __ffs((int)msk) - 1) {
                #pragma unroll
                for (int q = 0; q < 15; ++q) lst[q] = lst[q + 1];
                lst[15] = SENT;
            }
            nIdx[r] = (best == SENT) ? INVIDX : (unsigned)(best & 0xFFFFFFFFull);
        }

        // batched gather: 16 independent feature-row loads in flight
        const float* feat = ((src == 0) ? fa : fb) + (size_t)b * NS * C;
        float4 acc = make_float4(0.f, 0.f, 0.f, 0.f);
        #pragma unroll
        for (int r = 0; r < 16; ++r) {
            unsigned idx = nIdx[r];
            unsigned safe = (idx == INVIDX) ? 0u : idx;
            float ww = (idx == INVIDX) ? 0.f : __ldg(&knn_w[src * 16 + r]);
            float4 v = *(const float4*)(feat + (size_t)safe * C + lane * 4);
            acc.x += ww * v.x; acc.y += ww * v.y; acc.z += ww * v.z; acc.w += ww * v.w;
        }
        float bb = knn_b[src];
        float* dst = &smf[src][klocal][lane * 4];
        dst[0] = acc.x + bb; dst[1] = acc.y + bb; dst[2] = acc.z + bb; dst[3] = acc.w + bb;
    }
    __syncthreads();

    // ---- phase 2: kw MLP (4x128 @ 128x64), logits, softmax, fused build ----
    if (tid < 256) {
        int k = tid >> 6, j = tid & 63;
        float a = 0.f;
        #pragma unroll 8
        for (int i = 0; i < 128; ++i) a += kf[k][i] * __ldg(&kw1[i * 64 + j]);
        a = a * kg1[j] + kb1[j];
        h64[k][j] = a > 0.f ? a : 0.f;
    }
    __syncthreads();
    if (tid < 12) {
        int k = tid / 3, j = tid - k * 3;
        float a = 0.f;
        #pragma unroll 8
        for (int i = 0; i < 64; ++i) a += h64[k][i] * kw2[i * 3 + j];
        logit[k][j] = a + kb2[j];
    }
    __syncthreads();
    if (tid < KPB) {
        float l0 = logit[tid][0], l1 = logit[tid][1], l2 = logit[tid][2];
        float m = fmaxf(l0, fmaxf(l1, l2));
        float e0 = expf(l0 - m), e1 = expf(l1 - m), e2 = expf(l2 - m);
        float s = e0 + e1 + e2;
        swx[tid][0] = e0 / s; swx[tid][1] = e1 / s; swx[tid][2] = e2 / s;
    }
    __syncthreads();
    if (tid < 512) {
        int k = tid >> 7, c = tid & 127;
        float x = kf[k][c];
        float kv = swx[k][0] * x;
        float fs = kv * smf[0][k][c];
        kv = swx[k][1] * kv;
        fs += kv * smf[1][k][c];
        sFt[c][k] = fs;            // transposed store: [col][row]
        sFt[128 + c][k] = kv;
    }
    __syncthreads();

    // ---- phase 3a: partial H over k-halves, packed f32x2 ----
    {
        const int kh = tid >> 8;           // 0/1 -> i in [kh*128, kh*128+128)
        const int c = tid & 255;
        const int ib = kh * 128;
        unsigned long long a01 = 0ull, a23 = 0ull;   // rows (0,1) and (2,3)
        #pragma unroll 8
        for (int i = 0; i < 128; ++i) {
            float wv = __ldg(&fw1[(ib + i) * 256 + c]);
            unsigned long long wp = bcast2(wv);
            ulonglong2 xv = *(const ulonglong2*)&sFt[ib + i][0];
            fma2(a01, xv.x, wp);
            fma2(a23, xv.y, wp);
        }
        float2 v01 = up2(a01), v23 = up2(a23);
        pH[kh][0][c] = v01.x; pH[kh][1][c] = v01.y;
        pH[kh][2][c] = v23.x; pH[kh][3][c] = v23.y;
    }
    __syncthreads();
    // combine + BN + ReLU, store TRANSPOSED: 1024 outputs over 512 threads
    #pragma unroll
    for (int q = 0; q < 2; ++q) {
        int idx = tid + q * 512;
        int r = idx >> 8, c = idx & 255;
        float h = (pH[0][r][c] + pH[1][r][c]) * fg1[c] + fb1[c];
        sHt[c][r] = h > 0.f ? h : 0.f;
    }
    __syncthreads();

    // ---- phase 3b: out partials over k-quarters, packed f32x2 ----
    {
        const int c = tid & 127, kh = tid >> 7;   // kh 0..3, i in [kh*64, +64)
        const int ib = kh * 64;
        unsigned long long a01 = 0ull, a23 = 0ull;
        #pragma unroll 8
        for (int i = 0; i < 64; ++i) {
            float wv = __ldg(&fw2[(ib + i) * 128 + c]);
            unsigned long long wp = bcast2(wv);
            ulonglong2 xv = *(const ulonglong2*)&sHt[ib + i][0];
            fma2(a01, xv.x, wp);
            fma2(a23, xv.y, wp);
        }
        float2 v01 = up2(a01), v23 = up2(a23);
        pO[kh][0][c] = v01.x; pO[kh][1][c] = v01.y;
        pO[kh][2][c] = v23.x; pO[kh][3][c] = v23.y;
    }
    __syncthreads();
    // combine + bias -> out: 512 outputs, 1 per thread
    {
        const int r = tid >> 7, c = tid & 127;
        float o = pO[0][r][c] + pO[1][r][c] + pO[2][r][c] + pO[3][r][c] + fb2[c];
        outF[OUT_OFF + (size_t)(g0 + r) * 128 + c] = o;
    }
}

// ---------------- launch ----------------
extern "C" void kernel_launch(void* const* d_in, const int* in_sizes, int n_in,
                              void* d_out, int out_size)
{
    const float* fusion_feat = (const float*)d_in[0];
    const float* src_feat_a  = (const float*)d_in[1];
    const float* src_feat_b  = (const float*)d_in[2];
    const float* heat_w1 = (const float*)d_in[3];
    const float* heat_g1 = (const float*)d_in[4];
    const float* heat_b1 = (const float*)d_in[5];
    const float* heat_w2 = (const float*)d_in[6];
    const float* heat_b2 = (const float*)d_in[7];
    const float* knn_w = (const float*)d_in[8];
    const float* knn_b = (const float*)d_in[9];
    const float* kw_w1 = (const float*)d_in[10];
    const float* kw_g1 = (const float*)d_in[11];
    const float* kw_b1 = (const float*)d_in[12];
    const float* kw_w2 = (const float*)d_in[13];
    const float* kw_b2 = (const float*)d_in[14];
    const float* fuse_w1 = (const float*)d_in[15];
    const float* fuse_g1 = (const float*)d_in[16];
    const float* fuse_b1 = (const float*)d_in[17];
    const float* fuse_w2 = (const float*)d_in[18];
    const float* fuse_b2 = (const float*)d_in[19];
    const int* fusion_coords = (const int*)d_in[20];
    const int* src_coords_a  = (const int*)d_in[21];
    const int* src_coords_b  = (const int*)d_in[22];
    float* outF = (float*)d_out;

    cudaFuncSetAttribute(heat_kernel, cudaFuncAttributeMaxDynamicSharedMemorySize, HEAT_SMEM);
    cudaFuncSetAttribute(topk_kernel, cudaFuncAttributeMaxDynamicSharedMemorySize, TOPK_SMEM);

    cellreset_kernel<<<(2 * B * NCELLMAX + 1023) / 1024, 1024>>>();
    heat_kernel<<<NROWS / 64, 256, HEAT_SMEM>>>(fusion_feat, heat_w1, heat_g1,
                                                heat_b1, heat_w2, heat_b2,
                                                src_coords_a, src_coords_b, outF);
    topk_kernel<<<B, 1024, TOPK_SMEM>>>(fusion_coords, outF);
    megafuse_kernel<<<NK_TOT / KPB, 512>>>(src_feat_a, src_feat_b, knn_w, knn_b,
                                           fusion_feat, kw_w1, kw_g1, kw_b1,
                                           kw_w2, kw_b2, fuse_w1, fuse_g1,
                                           fuse_b1, fuse_w2, fuse_b2, outF);
}